// round 1
// baseline (speedup 1.0000x reference)
#include <cuda_runtime.h>
#include <cuda_bf16.h>
#include <cstdint>

#define N_NODES 50000
#define N_EDGES 800000
#define D 128

// Scratch for support = X @ W  (25.6 MB). Device global: no allocation APIs.
__device__ float g_support[(size_t)N_NODES * D];

// ---------------------------------------------------------------------------
// Kernel 1: init output with bias (harness poisons d_out to 0xAA)
// ---------------------------------------------------------------------------
__global__ void init_out_kernel(float* __restrict__ out, const float* __restrict__ bias) {
    int i = blockIdx.x * blockDim.x + threadIdx.x;
    if (i < N_NODES * D) {
        out[i] = bias[i & (D - 1)];
    }
}

// ---------------------------------------------------------------------------
// Kernel 2: support = X @ W
// Block tile: 128 rows x 128 cols (full W). Both tiles in smem, 8x8 per thread.
// ---------------------------------------------------------------------------
#define TILE_M 128
#define LDS_PAD 132   // 128 + 4 floats padding (bank-conflict mitigation, keeps 16B align)
#define GEMM_SMEM_BYTES (2 * TILE_M * LDS_PAD * 4)

__global__ __launch_bounds__(256, 1)
void gemm_kernel(const float* __restrict__ X,
                 const float* __restrict__ W,
                 float* __restrict__ sup) {
    extern __shared__ float smem[];
    float* Xs = smem;                      // [128][LDS_PAD]  Xs[r][k]
    float* Wt = smem + TILE_M * LDS_PAD;   // [128][LDS_PAD]  Wt[c][k] (transposed)

    const int tid  = threadIdx.x;
    const int row0 = blockIdx.x * TILE_M;

    // Load X tile (float4, coalesced). Out-of-range rows -> zeros.
    for (int idx = tid; idx < TILE_M * (D / 4); idx += 256) {
        int r  = idx >> 5;      // /32 float4s per row
        int c4 = idx & 31;
        float4 v = make_float4(0.f, 0.f, 0.f, 0.f);
        int gr = row0 + r;
        if (gr < N_NODES)
            v = *(const float4*)(X + (size_t)gr * D + c4 * 4);
        float* dst = Xs + r * LDS_PAD + c4 * 4;
        dst[0] = v.x; dst[1] = v.y; dst[2] = v.z; dst[3] = v.w;
    }

    // Load W transposed into Wt[c][k] (one-time scalar scatter is fine).
    for (int idx = tid; idx < D * (D / 4); idx += 256) {
        int k  = idx >> 5;
        int c4 = idx & 31;
        float4 v = *(const float4*)(W + k * D + c4 * 4);
        Wt[(c4 * 4 + 0) * LDS_PAD + k] = v.x;
        Wt[(c4 * 4 + 1) * LDS_PAD + k] = v.y;
        Wt[(c4 * 4 + 2) * LDS_PAD + k] = v.z;
        Wt[(c4 * 4 + 3) * LDS_PAD + k] = v.w;
    }
    __syncthreads();

    const int ty = tid >> 4;   // 0..15 -> rows ty + 16*i
    const int tx = tid & 15;   // 0..15 -> cols tx + 16*j

    float acc[8][8];
    #pragma unroll
    for (int i = 0; i < 8; i++)
        #pragma unroll
        for (int j = 0; j < 8; j++)
            acc[i][j] = 0.f;

    #pragma unroll 2
    for (int k = 0; k < D; k += 4) {
        float4 xa[8], wb[8];
        #pragma unroll
        for (int i = 0; i < 8; i++)
            xa[i] = *(const float4*)(Xs + (ty + 16 * i) * LDS_PAD + k);
        #pragma unroll
        for (int j = 0; j < 8; j++)
            wb[j] = *(const float4*)(Wt + (tx + 16 * j) * LDS_PAD + k);
        #pragma unroll
        for (int i = 0; i < 8; i++) {
            #pragma unroll
            for (int j = 0; j < 8; j++) {
                acc[i][j] += xa[i].x * wb[j].x;
                acc[i][j] += xa[i].y * wb[j].y;
                acc[i][j] += xa[i].z * wb[j].z;
                acc[i][j] += xa[i].w * wb[j].w;
            }
        }
    }

    #pragma unroll
    for (int i = 0; i < 8; i++) {
        int gr = row0 + ty + 16 * i;
        if (gr < N_NODES) {
            #pragma unroll
            for (int j = 0; j < 8; j++) {
                sup[(size_t)gr * D + tx + 16 * j] = acc[i][j];
            }
        }
    }
}

// ---------------------------------------------------------------------------
// Kernel 3: scatter-add. One warp per edge; lane l handles cols [4l, 4l+4).
// Vector red.global.add.v4.f32 -> 32 L2 RED ops per edge instead of 128.
// ---------------------------------------------------------------------------
__global__ __launch_bounds__(256)
void scatter_kernel(const int* __restrict__ ei,
                    const float* __restrict__ ew,
                    const float* __restrict__ sup,
                    float* __restrict__ out) {
    int e = blockIdx.x * 8 + (threadIdx.x >> 5);
    if (e >= N_EDGES) return;
    int lane = threadIdx.x & 31;

    int   row = __ldg(ei + e);            // destination
    int   col = __ldg(ei + N_EDGES + e);  // source
    float w   = __ldg(ew + e);

    float4 v = *(const float4*)(sup + (size_t)col * D + lane * 4);
    float* dst = out + (size_t)row * D + lane * 4;

    asm volatile("red.global.add.v4.f32 [%0], {%1, %2, %3, %4};"
                 :: "l"(dst), "f"(v.x * w), "f"(v.y * w), "f"(v.z * w), "f"(v.w * w)
                 : "memory");
}

// ---------------------------------------------------------------------------
extern "C" void kernel_launch(void* const* d_in, const int* in_sizes, int n_in,
                              void* d_out, int out_size) {
    const float* X    = (const float*)d_in[0];   // [N_NODES, D]
    const int*   ei   = (const int*)  d_in[1];   // [2, N_EDGES]
    const float* ew   = (const float*)d_in[2];   // [N_EDGES]
    const float* W    = (const float*)d_in[3];   // [D, D]
    const float* bias = (const float*)d_in[4];   // [D]
    float* out = (float*)d_out;

    float* sup;
    cudaGetSymbolAddress((void**)&sup, g_support);

    cudaFuncSetAttribute(gemm_kernel, cudaFuncAttributeMaxDynamicSharedMemorySize,
                         GEMM_SMEM_BYTES);

    // 1) out = bias (broadcast)
    {
        int total = N_NODES * D;
        init_out_kernel<<<(total + 255) / 256, 256>>>(out, bias);
    }
    // 2) support = X @ W
    {
        int grid = (N_NODES + TILE_M - 1) / TILE_M;  // 391
        gemm_kernel<<<grid, 256, GEMM_SMEM_BYTES>>>(X, W, sup);
    }
    // 3) out[row] += support[col] * ew  (atomic scatter)
    {
        int grid = (N_EDGES + 7) / 8;  // 100000 blocks, 8 warps each
        scatter_kernel<<<grid, 256>>>(ei, ew, sup, out);
    }
}